// round 12
// baseline (speedup 1.0000x reference)
#include <cuda_runtime.h>
#include <cstdint>

// EmbeddingWithDropout:
//   out[t, :] = weight[x[t], :] * ((u[x[t]] >= 0.1f) ? (1.0f/0.9f) : 0.0f)
// x: int32 [131072], weight: f32 [100000,128], u: f32 [100000], out: f32 [131072,128]
//
// Round-11: combine the two best-measured ingredients:
//   * persistent software-pipelined structure (R9: best kernel-side dur,
//     16.83us — chain head hidden, continuous rather than bursty load pressure)
//   * __stcs streaming stores (R3/R4: best bench, 16.86us — output stream is
//     the L2 eviction victim, weight table stays resident across graph replays)
// Evidence says bench time ~= output DRAM drain (67MB @ ~4TB/s eff.); if these
// are additive at all the gain is small, but every other lever measured neutral
// or negative. No predication (tested dead under both store policies).

#define TPW 4  // tokens per warp-chunk

__global__ void __launch_bounds__(256, 4)
embedding_dropout_kernel(const int* __restrict__ x,
                         const float4* __restrict__ weight,   // [vocab*32] float4
                         const float* __restrict__ u,         // [vocab]
                         float4* __restrict__ out,            // [n_tok*32] float4
                         int n_tok, int nchunks, int cstride)
{
    const int lane = threadIdx.x & 31;
    int c = blockIdx.x * (blockDim.x >> 5) + (threadIdx.x >> 5);

    int   rows[TPW];
    float uv[TPW];

    // Prologue: indices + u for the first chunk.
    if (c < nchunks) {
        const int base = c * TPW;
        #pragma unroll
        for (int i = 0; i < TPW; i++) {
            const int tok = base + i;
            rows[i] = (tok < n_tok) ? __ldg(&x[tok]) : 0;
        }
        #pragma unroll
        for (int i = 0; i < TPW; i++)
            uv[i] = __ldg(&u[rows[i]]);
    }

    while (c < nchunks) {
        const int base = c * TPW;

        // Issue this chunk's row gathers (expensive wave).
        float4 v[TPW];
        #pragma unroll
        for (int i = 0; i < TPW; i++)
            v[i] = __ldg(&weight[(size_t)rows[i] * 32 + lane]);

        // Overlap: NEXT chunk's indices + u while gathers are in flight.
        const int cn = c + cstride;
        int   rowsN[TPW];
        float uvN[TPW];
        if (cn < nchunks) {
            const int bn = cn * TPW;
            #pragma unroll
            for (int i = 0; i < TPW; i++) {
                const int tok = bn + i;
                rowsN[i] = (tok < n_tok) ? __ldg(&x[tok]) : 0;
            }
            #pragma unroll
            for (int i = 0; i < TPW; i++)
                uvN[i] = __ldg(&u[rowsN[i]]);
        }

        // Scale + STREAMING store (first consumer of the gathers).
        #pragma unroll
        for (int i = 0; i < TPW; i++) {
            const float keep = (uv[i] >= 0.1f) ? (1.0f / 0.9f) : 0.0f;
            v[i].x *= keep;
            v[i].y *= keep;
            v[i].z *= keep;
            v[i].w *= keep;
            const int tok = base + i;
            if (tok < n_tok)
                __stcs(&out[(size_t)tok * 32 + lane], v[i]);
        }

        // Rotate pipeline.
        #pragma unroll
        for (int i = 0; i < TPW; i++) {
            rows[i] = rowsN[i];
            uv[i]   = uvN[i];
        }
        c = cn;
    }
}

extern "C" void kernel_launch(void* const* d_in, const int* in_sizes, int n_in,
                              void* d_out, int out_size)
{
    const int*    x      = (const int*)d_in[0];
    const float4* weight = (const float4*)d_in[1];
    const float*  u      = (const float*)d_in[2];
    float4*       out    = (float4*)d_out;

    const int n_tok = in_sizes[0];                     // 131072
    const int threads = 256;                           // 8 warps/block
    const int blocks  = 148 * 4;                       // persistent: 4 CTAs/SM
    const int warps_total = blocks * (threads / 32);   // 4736
    const int nchunks = (n_tok + TPW - 1) / TPW;       // 32768

    embedding_dropout_kernel<<<blocks, threads>>>(x, weight, u, out,
                                                  n_tok, nchunks, warps_total);
}

// round 13
// speedup vs baseline: 1.0152x; 1.0152x over previous
#include <cuda_runtime.h>
#include <cstdint>

// EmbeddingWithDropout:
//   out[t, :] = weight[x[t], :] * ((u[x[t]] >= 0.1f) ? (1.0f/0.9f) : 0.0f)
// x: int32 [131072], weight: f32 [100000,128], u: f32 [100000], out: f32 [131072,128]
//
// Champion config (R4, 16.864us bench, reproduced 2x) + one micro-tweak.
//
// Steady-state model established over R3-R11: with __stcs streaming stores the
// 51MB weight table stays L2-resident across graph replays and bench time ==
// compulsory output drain to DRAM (67MB / 16.86us = 3.98TB/s ~= HBM write-path
// ceiling). All concurrency/issue/traffic levers measured neutral or negative:
// persistent pipeline (-0.3us), predication (-0.25us), wt (-2.7us), plain
// stores (-2.1us), v8+evict hints (-0.3us).
//
// R12 tweak: weight gathers use __ldcg (L2-only, no L1 allocate). Random 512B
// gathers over 51MB have ~0% L1 hit rate; skipping L1 allocation removes L1tex
// churn and keeps x/u lines resident in L1. Zero-risk micro-opt.

#define TOK_PER_WARP 8

__global__ void __launch_bounds__(256, 4)
embedding_dropout_kernel(const int* __restrict__ x,
                         const float4* __restrict__ weight,   // [vocab*32] float4
                         const float* __restrict__ u,         // [vocab]
                         float4* __restrict__ out,            // [n_tok*32] float4
                         int n_tok)
{
    const int gtid = blockIdx.x * blockDim.x + threadIdx.x;
    const int warp = gtid >> 5;
    const int lane = threadIdx.x & 31;
    const int base = warp * TOK_PER_WARP;
    if (base >= n_tok) return;

    if (base + TOK_PER_WARP <= n_tok) {
        // ---- Wave 1: 8 independent index loads (uniform broadcast, L1-cached) ----
        int rows[TOK_PER_WARP];
        #pragma unroll
        for (int i = 0; i < TOK_PER_WARP; i++)
            rows[i] = __ldg(&x[base + i]);

        // ---- Wave 2: 8 u-loads + 8 row-gathers, all independent ----
        //      u: L1-cached (tiny, reused); weight: L2-only (no L1 allocate).
        float uv[TOK_PER_WARP];
        float4 v[TOK_PER_WARP];
        #pragma unroll
        for (int i = 0; i < TOK_PER_WARP; i++) {
            uv[i] = __ldg(&u[rows[i]]);
            v[i]  = __ldcg(&weight[(size_t)rows[i] * 32 + lane]);
        }

        // ---- Scale + STREAMING store (output = L2 eviction victim) ----
        #pragma unroll
        for (int i = 0; i < TOK_PER_WARP; i++) {
            const float keep = (uv[i] >= 0.1f) ? (1.0f / 0.9f) : 0.0f;
            v[i].x *= keep;
            v[i].y *= keep;
            v[i].z *= keep;
            v[i].w *= keep;
            __stcs(&out[(size_t)(base + i) * 32 + lane], v[i]);
        }
    } else {
        // ---- Tail path ----
        for (int i = 0; base + i < n_tok; i++) {
            const int row = __ldg(&x[base + i]);
            const float keep = (__ldg(&u[row]) >= 0.1f) ? (1.0f / 0.9f) : 0.0f;
            float4 v = __ldcg(&weight[(size_t)row * 32 + lane]);
            v.x *= keep; v.y *= keep; v.z *= keep; v.w *= keep;
            __stcs(&out[(size_t)(base + i) * 32 + lane], v);
        }
    }
}

extern "C" void kernel_launch(void* const* d_in, const int* in_sizes, int n_in,
                              void* d_out, int out_size)
{
    const int*    x      = (const int*)d_in[0];
    const float4* weight = (const float4*)d_in[1];
    const float*  u      = (const float*)d_in[2];
    float4*       out    = (float4*)d_out;

    const int n_tok = in_sizes[0];                            // 131072
    const int threads = 256;                                  // 8 warps/block
    const int tok_per_block = (threads / 32) * TOK_PER_WARP;  // 64
    const int blocks = (n_tok + tok_per_block - 1) / tok_per_block;

    embedding_dropout_kernel<<<blocks, threads>>>(x, weight, u, out, n_tok);
}